// round 4
// baseline (speedup 1.0000x reference)
#include <cuda_runtime.h>

#define B_    2
#define N_    512
#define DS_   384
#define DP_   128
#define H_    16
#define DH_   64
#define DI_   1024
#define MAXS_ 2048

// ---------------- scratch (static device globals; no allocs) ----------------
__device__ float g_bias[B_*H_*N_*N_];   // attn bias  [b][h][i][j]
__device__ float g_q[B_*H_*N_*DH_];     // [b][h][n][d]
__device__ float g_k[B_*H_*N_*DH_];
__device__ float g_v[B_*H_*N_*DH_];
__device__ float g_g[B_*N_*DI_];        // gate logits [b][n][di]
__device__ float g_o[B_*N_*DI_];        // attention out [b][n][di]

// ---------------------------------------------------------------------------
// K1: fused LayerNorm + per-head bias projection + positional bias
//   bias[b,h,i,j] = rstd*( dot(p, W'[:,h]) - mu*c1[h] ) + c2[h] + abb[i,j]
// block: 256 threads, one (b,i); thread t handles j=t and j=t+256.
// ---------------------------------------------------------------------------
__global__ __launch_bounds__(256) void k1_ln_bias(
    const float* __restrict__ pw, const float* __restrict__ gamma,
    const float* __restrict__ beta, const float* __restrict__ wb,
    const float* __restrict__ abb)
{
    __shared__ float Wt[H_][DP_];
    __shared__ float c1s[H_], c2s[H_];
    int tid = threadIdx.x;

    for (int idx = tid; idx < DP_*H_; idx += 256) {
        int d = idx >> 4, h = idx & 15;
        Wt[h][d] = gamma[d] * wb[d*H_ + h];
    }
    __syncthreads();
    if (tid < H_) {
        float a = 0.f, c = 0.f;
        for (int d = 0; d < DP_; d++) {
            a += Wt[tid][d];
            c += beta[d] * wb[d*H_ + tid];
        }
        c1s[tid] = a; c2s[tid] = c;
    }
    __syncthreads();

    int bi = blockIdx.x;            // b*N + i
    int i  = bi & (N_-1);
    int b  = bi >> 9;
    int j0 = tid;

    const float* row0 = pw + ((long)bi * N_ + j0) * DP_;
    const float* row1 = row0 + 256 * DP_;

    float acc0[H_], acc1[H_];
#pragma unroll
    for (int h = 0; h < H_; h++) { acc0[h] = 0.f; acc1[h] = 0.f; }
    float s10 = 0.f, s20 = 0.f, s11 = 0.f, s21 = 0.f;

    for (int dg = 0; dg < DP_/4; dg++) {
        float4 p0 = __ldg((const float4*)row0 + dg);
        float4 p1 = __ldg((const float4*)row1 + dg);
        s10 += p0.x + p0.y + p0.z + p0.w;
        s20 += p0.x*p0.x + p0.y*p0.y + p0.z*p0.z + p0.w*p0.w;
        s11 += p1.x + p1.y + p1.z + p1.w;
        s21 += p1.x*p1.x + p1.y*p1.y + p1.z*p1.z + p1.w*p1.w;
#pragma unroll
        for (int h = 0; h < H_; h++) {
            float4 w = *(const float4*)(&Wt[h][dg*4]);
            acc0[h] += p0.x*w.x + p0.y*w.y + p0.z*w.z + p0.w*w.w;
            acc1[h] += p1.x*w.x + p1.y*w.y + p1.z*w.z + p1.w*w.w;
        }
    }

    float mu0 = s10 * (1.f/DP_);
    float mu1 = s11 * (1.f/DP_);
    float r0  = rsqrtf(s20*(1.f/DP_) - mu0*mu0 + 1e-5f);
    float r1  = rsqrtf(s21*(1.f/DP_) - mu1*mu1 + 1e-5f);
    float pb0 = abb[i*MAXS_ + j0];
    float pb1 = abb[i*MAXS_ + j0 + 256];

    int base = ((b*H_)*N_ + i)*N_;
#pragma unroll
    for (int h = 0; h < H_; h++) {
        int o = base + h*(N_*N_);
        g_bias[o + j0]       = r0*(acc0[h] - mu0*c1s[h]) + c2s[h] + pb0;
        g_bias[o + j0 + 256] = r1*(acc1[h] - mu1*c1s[h]) + c2s[h] + pb1;
    }
}

// ---------------------------------------------------------------------------
// K2: QKV+G projections.  C = X[1024x384] @ W[z][384x1024].
// 128x128 tile, BK=8, 256 threads, 8x8 microtile. grid (8,8,4).
// ---------------------------------------------------------------------------
__global__ __launch_bounds__(256) void k2_qkvg(
    const float* __restrict__ X,
    const float* __restrict__ wq, const float* __restrict__ wk,
    const float* __restrict__ wv, const float* __restrict__ wg)
{
    __shared__ float As[8][128];
    __shared__ float Bs[8][128];
    int z = blockIdx.z;
    const float* W = (z==0) ? wq : (z==1) ? wk : (z==2) ? wv : wg;
    int m0 = blockIdx.y * 128, n0 = blockIdx.x * 128;
    int tid = threadIdx.x;
    int tx = tid & 15, ty = tid >> 4;

    float acc[8][8];
#pragma unroll
    for (int a = 0; a < 8; a++)
#pragma unroll
        for (int c = 0; c < 8; c++) acc[a][c] = 0.f;

    int ar = tid >> 1, ac = (tid & 1) * 4;
    int bk = tid >> 5, bc = (tid & 31) * 4;

    for (int k0 = 0; k0 < DS_; k0 += 8) {
        float4 av = *(const float4*)(X + (m0+ar)*DS_ + k0 + ac);
        float4 bv = *(const float4*)(W + (k0+bk)*DI_ + n0 + bc);
        __syncthreads();
        As[ac+0][ar] = av.x; As[ac+1][ar] = av.y;
        As[ac+2][ar] = av.z; As[ac+3][ar] = av.w;
        *(float4*)(&Bs[bk][bc]) = bv;
        __syncthreads();
#pragma unroll
        for (int k = 0; k < 8; k++) {
            float a[8], bb[8];
            *(float4*)(&a[0])  = *(const float4*)(&As[k][ty*8]);
            *(float4*)(&a[4])  = *(const float4*)(&As[k][ty*8+4]);
            *(float4*)(&bb[0]) = *(const float4*)(&Bs[k][tx*8]);
            *(float4*)(&bb[4]) = *(const float4*)(&Bs[k][tx*8+4]);
#pragma unroll
            for (int im = 0; im < 8; im++)
#pragma unroll
                for (int in = 0; in < 8; in++)
                    acc[im][in] += a[im]*bb[in];
        }
    }

    if (z == 3) {
#pragma unroll
        for (int im = 0; im < 8; im++) {
            int m = m0 + ty*8 + im;
#pragma unroll
            for (int in = 0; in < 8; in++)
                g_g[m*DI_ + n0 + tx*8 + in] = acc[im][in];
        }
    } else {
        float* dst = (z==0) ? g_q : (z==1) ? g_k : g_v;
#pragma unroll
        for (int im = 0; im < 8; im++) {
            int m = m0 + ty*8 + im;
            int b = m >> 9, n = m & (N_-1);
#pragma unroll
            for (int in = 0; in < 8; in++) {
                int col = n0 + tx*8 + in;
                int h = col >> 6, dh = col & 63;
                dst[((b*H_ + h)*N_ + n)*DH_ + dh] = acc[im][in];
            }
        }
    }
}

// ---------------------------------------------------------------------------
// K35: fused attention per (b,h): scores + bias + online softmax + P@V.
// BM=64 i-rows per block, j in chunks of 32. No scores in DRAM.
// 256 threads: ti=tid>>4 (4 i-rows), tj=tid&15 (2 j-cols / 4 d-cols).
// grid (N/64=8, B*H=32).
// NOTE: Qs/Ks/Ps use pitch 65 (conflict-free reads); all smem stores into
// pitch-65 arrays are SCALAR (odd rows are not 16B-aligned -> no STS.128).
// ---------------------------------------------------------------------------
__global__ __launch_bounds__(256) void k35_attn()
{
    __shared__ float Qs[64][65];
    __shared__ float Ks[32][65];
    __shared__ float Vs[32][64];
    __shared__ float Ps[32][65];

    int z  = blockIdx.y;                    // b*16 + h
    int i0 = blockIdx.x * 64;
    const float* Q  = g_q + (long)z * (N_*DH_);
    const float* K  = g_k + (long)z * (N_*DH_);
    const float* V  = g_v + (long)z * (N_*DH_);
    const float* Bb = g_bias + (long)z * N_ * N_;

    int tid = threadIdx.x;
    int ti = tid >> 4;      // 0..15 -> rows ti*4..ti*4+3
    int tj = tid & 15;      // 0..15

    // Load Q tile [64][64] -> Qs (vector LDG, scalar STS: pitch 65)
    {
        int r  = tid >> 2;          // 0..63
        int c0 = (tid & 3) * 16;    // 16 cols = 4 float4
#pragma unroll
        for (int q = 0; q < 4; q++) {
            float4 v = *(const float4*)(Q + (i0 + r)*DH_ + c0 + q*4);
            Qs[r][c0 + q*4 + 0] = v.x;
            Qs[r][c0 + q*4 + 1] = v.y;
            Qs[r][c0 + q*4 + 2] = v.z;
            Qs[r][c0 + q*4 + 3] = v.w;
        }
    }

    float m_run[4], l_run[4], o[4][4];
#pragma unroll
    for (int a = 0; a < 4; a++) {
        m_run[a] = -1e30f; l_run[a] = 0.f;
#pragma unroll
        for (int c = 0; c < 4; c++) o[a][c] = 0.f;
    }
    __syncthreads();

    for (int j0 = 0; j0 < N_; j0 += 32) {
        // Load K,V chunk [32][64]. Ks scalar stores (pitch 65), Vs vector.
        {
            int r = tid >> 3;            // 0..31
            int c = (tid & 7) * 8;       // 8 floats
            float4 ka = *(const float4*)(K + (j0 + r)*DH_ + c);
            float4 kb = *(const float4*)(K + (j0 + r)*DH_ + c + 4);
            float4 va = *(const float4*)(V + (j0 + r)*DH_ + c);
            float4 vb = *(const float4*)(V + (j0 + r)*DH_ + c + 4);
            Ks[r][c+0] = ka.x; Ks[r][c+1] = ka.y; Ks[r][c+2] = ka.z; Ks[r][c+3] = ka.w;
            Ks[r][c+4] = kb.x; Ks[r][c+5] = kb.y; Ks[r][c+6] = kb.z; Ks[r][c+7] = kb.w;
            *(float4*)(&Vs[r][c])   = va;
            *(float4*)(&Vs[r][c+4]) = vb;
        }
        __syncthreads();

        // S = Q K^T  (4 rows x 2 cols per thread)
        float s[4][2];
#pragma unroll
        for (int a = 0; a < 4; a++) { s[a][0] = 0.f; s[a][1] = 0.f; }
#pragma unroll 8
        for (int k = 0; k < 64; k++) {
            float a0 = Qs[ti*4+0][k], a1 = Qs[ti*4+1][k];
            float a2 = Qs[ti*4+2][k], a3 = Qs[ti*4+3][k];
            float b0 = Ks[tj*2+0][k], b1 = Ks[tj*2+1][k];
            s[0][0] += a0*b0; s[0][1] += a0*b1;
            s[1][0] += a1*b0; s[1][1] += a1*b1;
            s[2][0] += a2*b0; s[2][1] += a2*b1;
            s[3][0] += a3*b0; s[3][1] += a3*b1;
        }

        // scale + bias, online softmax update (rows partitioned over 16 tj lanes)
#pragma unroll
        for (int a = 0; a < 4; a++) {
            const float* br = Bb + (long)(i0 + ti*4 + a)*N_ + j0 + tj*2;
            s[a][0] = s[a][0]*0.125f + br[0];
            s[a][1] = s[a][1]*0.125f + br[1];

            float cm = fmaxf(s[a][0], s[a][1]);
#pragma unroll
            for (int sft = 8; sft > 0; sft >>= 1)
                cm = fmaxf(cm, __shfl_xor_sync(0xffffffffu, cm, sft, 16));
            float mn = fmaxf(m_run[a], cm);
            float sc = __expf(m_run[a] - mn);
            float e0 = __expf(s[a][0] - mn);
            float e1 = __expf(s[a][1] - mn);
            float cs = e0 + e1;
#pragma unroll
            for (int sft = 8; sft > 0; sft >>= 1)
                cs += __shfl_xor_sync(0xffffffffu, cs, sft, 16);
            l_run[a] = l_run[a]*sc + cs;
            m_run[a] = mn;
#pragma unroll
            for (int c = 0; c < 4; c++) o[a][c] *= sc;
            s[a][0] = e0; s[a][1] = e1;
        }

        // store P transposed: Ps[j][i] (scalar, pitch 65)
#pragma unroll
        for (int a = 0; a < 4; a++) {
            Ps[tj*2+0][ti*4+a] = s[a][0];
            Ps[tj*2+1][ti*4+a] = s[a][1];
        }
        __syncthreads();

        // O += P @ V  (k = j, 32)
#pragma unroll 8
        for (int j = 0; j < 32; j++) {
            float p0 = Ps[j][ti*4+0], p1 = Ps[j][ti*4+1];
            float p2 = Ps[j][ti*4+2], p3 = Ps[j][ti*4+3];
            float4 bv = *(const float4*)(&Vs[j][tj*4]);
            o[0][0] += p0*bv.x; o[0][1] += p0*bv.y; o[0][2] += p0*bv.z; o[0][3] += p0*bv.w;
            o[1][0] += p1*bv.x; o[1][1] += p1*bv.y; o[1][2] += p1*bv.z; o[1][3] += p1*bv.w;
            o[2][0] += p2*bv.x; o[2][1] += p2*bv.y; o[2][2] += p2*bv.z; o[2][3] += p2*bv.w;
            o[3][0] += p3*bv.x; o[3][1] += p3*bv.y; o[3][2] += p3*bv.z; o[3][3] += p3*bv.w;
        }
        __syncthreads();
    }

    // epilogue: normalize, write [b][n][h*64+d]
    int b = z >> 4, h = z & 15;
#pragma unroll
    for (int a = 0; a < 4; a++) {
        float inv = 1.f / l_run[a];
        int i = i0 + ti*4 + a;
#pragma unroll
        for (int c = 0; c < 4; c++)
            g_o[(long)(b*N_ + i)*DI_ + h*DH_ + tj*4 + c] = o[a][c] * inv;
    }
}

// ---------------------------------------------------------------------------
// K6: out = (o * sigmoid(g)) @ w_o[1024x384]. BM=64,BN=64,BK=16, 4x4 micro.
// sigmoid gating fused into A-tile load. grid (6,16).
// ---------------------------------------------------------------------------
__global__ __launch_bounds__(256) void k6_out(
    const float* __restrict__ wo, float* __restrict__ out)
{
    __shared__ float As[16][68];
    __shared__ float Bs[16][64];
    int m0 = blockIdx.y * 64, n0 = blockIdx.x * 64;
    int tid = threadIdx.x;
    int tx = tid & 15, ty = tid >> 4;
    int ar = tid >> 2, ac = (tid & 3) * 4;
    int bk = tid >> 4, bc = (tid & 15) * 4;

    float acc[4][4];
#pragma unroll
    for (int a = 0; a < 4; a++)
#pragma unroll
        for (int c = 0; c < 4; c++) acc[a][c] = 0.f;

    for (int k0 = 0; k0 < DI_; k0 += 16) {
        float4 ov = *(const float4*)(g_o + (m0+ar)*DI_ + k0 + ac);
        float4 gv = *(const float4*)(g_g + (m0+ar)*DI_ + k0 + ac);
        float4 bv = *(const float4*)(wo + (k0+bk)*DS_ + n0 + bc);
        float4 a;
        a.x = ov.x / (1.f + __expf(-gv.x));
        a.y = ov.y / (1.f + __expf(-gv.y));
        a.z = ov.z / (1.f + __expf(-gv.z));
        a.w = ov.w / (1.f + __expf(-gv.w));
        __syncthreads();
        As[ac+0][ar] = a.x; As[ac+1][ar] = a.y;
        As[ac+2][ar] = a.z; As[ac+3][ar] = a.w;
        *(float4*)(&Bs[bk][bc]) = bv;
        __syncthreads();
#pragma unroll
        for (int k = 0; k < 16; k++) {
            float4 av = *(const float4*)(&As[k][ty*4]);
            float4 b  = *(const float4*)(&Bs[k][tx*4]);
            acc[0][0] += av.x*b.x; acc[0][1] += av.x*b.y; acc[0][2] += av.x*b.z; acc[0][3] += av.x*b.w;
            acc[1][0] += av.y*b.x; acc[1][1] += av.y*b.y; acc[1][2] += av.y*b.z; acc[1][3] += av.y*b.w;
            acc[2][0] += av.z*b.x; acc[2][1] += av.z*b.y; acc[2][2] += av.z*b.z; acc[2][3] += av.z*b.w;
            acc[3][0] += av.w*b.x; acc[3][1] += av.w*b.y; acc[3][2] += av.w*b.z; acc[3][3] += av.w*b.w;
        }
    }

#pragma unroll
    for (int ii = 0; ii < 4; ii++)
#pragma unroll
        for (int jj = 0; jj < 4; jj++)
            out[(m0 + ty*4 + ii)*DS_ + n0 + tx*4 + jj] = acc[ii][jj];
}

// ---------------------------------------------------------------------------
extern "C" void kernel_launch(void* const* d_in, const int* in_sizes, int n_in,
                              void* d_out, int out_size) {
    const float* single = (const float*)d_in[0];
    const float* pw     = (const float*)d_in[1];
    const float* gamma  = (const float*)d_in[2];
    const float* beta   = (const float*)d_in[3];
    const float* wb     = (const float*)d_in[4];
    const float* abb    = (const float*)d_in[5];
    const float* wq     = (const float*)d_in[6];
    const float* wk     = (const float*)d_in[7];
    const float* wv     = (const float*)d_in[8];
    const float* wg     = (const float*)d_in[9];
    const float* wo     = (const float*)d_in[10];
    float* out = (float*)d_out;

    k1_ln_bias<<<B_*N_, 256>>>(pw, gamma, beta, wb, abb);
    k2_qkvg<<<dim3(8, 8, 4), 256>>>(single, wq, wk, wv, wg);
    k35_attn<<<dim3(8, 32), 256>>>();
    k6_out<<<dim3(6, 16), 256>>>(wo, out);
}